// round 9
// baseline (speedup 1.0000x reference)
#include <cuda_runtime.h>
#include <cuda_bf16.h>
#include <mma.h>
#include <math.h>
#include <stdint.h>

using namespace nvcuda;

#define B_   2
#define L_   4096
#define D_   1024
#define H_   16
#define HD_  64
#define CH_  128
#define NCH_ 32
#define BH_  32
#define TOK_ 8192
#define GTOK_ 8
#define NIT_ 64          // D_/16

// ---------------- scratch (device globals; addresses taken ONLY in device code) ----------------
__device__ float g_q [BH_*L_*HD_];
__device__ float g_k [BH_*L_*HD_];
__device__ float g_v [BH_*L_*HD_];
__device__ float g_state[2*BH_*NCH_*HD_*HD_];
__device__ float g_oc[TOK_*D_];
__device__ float g_beta[BH_*L_];
__device__ float g_fd [BH_*L_];
__device__ float g_sd [BH_*L_];
__device__ float g_fg [BH_*L_];
__device__ float g_sg [BH_*L_];
__device__ float g_psi[BH_*L_];
__device__ float g_dff[BH_*NCH_];
__device__ float g_dfs[BH_*NCH_];
__device__ float g_WT [80*D_];
// bf16 scratch as uint4 arrays -> guaranteed 16B alignment
__device__ uint4 g_xh4 [TOK_*D_/8];
__device__ uint4 g_xl4 [TOK_*D_/8];
__device__ uint4 g_och4[TOK_*D_/8];
__device__ uint4 g_ocl4[TOK_*D_/8];
__device__ uint4 g_wh4 [4*D_*D_/8];
__device__ uint4 g_wl4 [4*D_*D_/8];

__device__ __forceinline__ float sigm(float x){ return 1.0f/(1.0f+expf(-x)); }

// convert 8 floats (2 float4) -> packed hi uint4 + lo uint4 (8 bf16 each)
__device__ __forceinline__ void cvt8(const float4& a, const float4& b, uint4& H, uint4& Lo){
    __nv_bfloat16 h0=__float2bfloat16(a.x), h1=__float2bfloat16(a.y);
    __nv_bfloat16 h2=__float2bfloat16(a.z), h3=__float2bfloat16(a.w);
    __nv_bfloat16 h4=__float2bfloat16(b.x), h5=__float2bfloat16(b.y);
    __nv_bfloat16 h6=__float2bfloat16(b.z), h7=__float2bfloat16(b.w);
    __nv_bfloat162 p0=__halves2bfloat162(h0,h1), p1=__halves2bfloat162(h2,h3);
    __nv_bfloat162 p2=__halves2bfloat162(h4,h5), p3=__halves2bfloat162(h6,h7);
    H.x=*(uint32_t*)&p0; H.y=*(uint32_t*)&p1; H.z=*(uint32_t*)&p2; H.w=*(uint32_t*)&p3;
    __nv_bfloat16 l0=__float2bfloat16(a.x-__bfloat162float(h0));
    __nv_bfloat16 l1=__float2bfloat16(a.y-__bfloat162float(h1));
    __nv_bfloat16 l2=__float2bfloat16(a.z-__bfloat162float(h2));
    __nv_bfloat16 l3=__float2bfloat16(a.w-__bfloat162float(h3));
    __nv_bfloat16 l4=__float2bfloat16(b.x-__bfloat162float(h4));
    __nv_bfloat16 l5=__float2bfloat16(b.y-__bfloat162float(h5));
    __nv_bfloat16 l6=__float2bfloat16(b.z-__bfloat162float(h6));
    __nv_bfloat16 l7=__float2bfloat16(b.w-__bfloat162float(h7));
    __nv_bfloat162 q0=__halves2bfloat162(l0,l1), q1=__halves2bfloat162(l2,l3);
    __nv_bfloat162 q2=__halves2bfloat162(l4,l5), q3=__halves2bfloat162(l6,l7);
    Lo.x=*(uint32_t*)&q0; Lo.y=*(uint32_t*)&q1; Lo.z=*(uint32_t*)&q2; Lo.w=*(uint32_t*)&q3;
}

// ---------------- elementwise hi/lo split (buffers selected in device code) ----------------
// SEL 0: src = x (arg) -> g_xh/g_xl.  SEL 1: src = g_oc -> g_och/g_ocl.
template<int SEL>
__global__ __launch_bounds__(256) void split_pair_kernel(const float* __restrict__ srcArg){
    size_t g = (size_t)blockIdx.x*256 + threadIdx.x;    // one uint4 (8 elems) per thread
    const float4* s = (const float4*)((SEL==0) ? srcArg : (const float*)&g_oc[0]);
    uint4* dh = (SEL==0) ? &g_xh4[0] : &g_och4[0];
    uint4* dl = (SEL==0) ? &g_xl4[0] : &g_ocl4[0];
    float4 a = s[2*g], b = s[2*g+1];
    uint4 Hq, Lq; cvt8(a, b, Hq, Lq);
    dh[g] = Hq; dl[g] = Lq;
}

__global__ __launch_bounds__(256) void split_w_kernel(const float* __restrict__ W0, const float* __restrict__ W1,
                                                      const float* __restrict__ W2, const float* __restrict__ W3){
    int wsel = blockIdx.y;
    const float* W = (wsel==0)?W0:(wsel==1)?W1:(wsel==2)?W2:W3;
    uint4* dh = &g_wh4[0] + (size_t)wsel*D_*D_/8;
    uint4* dl = &g_wl4[0] + (size_t)wsel*D_*D_/8;
    size_t g = (size_t)blockIdx.x*256 + threadIdx.x;
    const float4* s = (const float4*)W;
    float4 a = s[2*g], b = s[2*g+1];
    uint4 Hq, Lq; cvt8(a, b, Hq, Lq);
    dh[g] = Hq; dl[g] = Lq;
}

// ---------------- transpose gate weights ----------------
__global__ void wt_kernel(const float* __restrict__ Wb,  const float* __restrict__ Wfd,
                          const float* __restrict__ Wsd, const float* __restrict__ Wfg,
                          const float* __restrict__ Wsg){
    int o = blockIdx.x;
    int g = o >> 4, h = o & 15;
    const float* W = (g==0)?Wb:(g==1)?Wfd:(g==2)?Wsd:(g==3)?Wfg:Wsg;
    for(int i = threadIdx.x; i < D_; i += blockDim.x)
        g_WT[o*D_ + i] = W[i*H_ + h];
}

// ---------------- WMMA bf16 split-GEMM, pre-split operands, double-buffered ----------------
// C = (Ah+Al)(Wh+Wl) ~= Ah*Wh + Ah*Wl + Al*Wh. 128x128 tile/CTA, BK=16, 8 warps of 64x32.
// All operand pointers resolved in device code from JOB.
template<int JOB>
__global__ __launch_bounds__(256) void wgemm_kernel(float* __restrict__ Cout){
    __shared__ __align__(16) __nv_bfloat16 sAh[2][128][24];
    __shared__ __align__(16) __nv_bfloat16 sAl[2][128][24];
    __shared__ __align__(16) __nv_bfloat16 sWh[2][16][136];
    __shared__ __align__(16) __nv_bfloat16 sWl[2][16][136];

    const __nv_bfloat16* Ah  = (const __nv_bfloat16*)((JOB==3) ? &g_och4[0] : &g_xh4[0]);
    const __nv_bfloat16* Al  = (const __nv_bfloat16*)((JOB==3) ? &g_ocl4[0] : &g_xl4[0]);
    const __nv_bfloat16* Wph = (const __nv_bfloat16*)(&g_wh4[0]) + (size_t)JOB*D_*D_;
    const __nv_bfloat16* Wpl = (const __nv_bfloat16*)(&g_wl4[0]) + (size_t)JOB*D_*D_;

    int tid = threadIdx.x, warp = tid >> 5;
    int wm = (warp >> 2) * 64, wn = (warp & 3) * 32;
    int rowBase = blockIdx.y * 128, colBase = blockIdx.x * 128;

    int ar = tid >> 1,  ac = (tid & 1) * 8;     // A: 128 rows x 16 k
    int wr = tid >> 4,  wc = (tid & 15) * 8;    // W: 16 k x 128 n
    const __nv_bfloat16* apbh = Ah  + (size_t)(rowBase + ar)*D_ + ac;
    const __nv_bfloat16* apbl = Al  + (size_t)(rowBase + ar)*D_ + ac;
    const __nv_bfloat16* wpbh = Wph + (size_t)wr*D_ + colBase + wc;
    const __nv_bfloat16* wpbl = Wpl + (size_t)wr*D_ + colBase + wc;

    wmma::fragment<wmma::accumulator,16,16,16,float> cf[4][2];
    #pragma unroll
    for(int mi=0;mi<4;mi++)
        #pragma unroll
        for(int nj=0;nj<2;nj++) wmma::fill_fragment(cf[mi][nj], 0.0f);

    // prologue
    *(uint4*)&sAh[0][ar][ac] = *(const uint4*)apbh;
    *(uint4*)&sAl[0][ar][ac] = *(const uint4*)apbl;
    *(uint4*)&sWh[0][wr][wc] = *(const uint4*)wpbh;
    *(uint4*)&sWl[0][wr][wc] = *(const uint4*)wpbl;
    __syncthreads();

    for (int it = 0; it < NIT_; it++){
        int buf = it & 1;
        uint4 rah, ral, rwh, rwl;
        if (it + 1 < NIT_){
            rah = *(const uint4*)(apbh + (it+1)*16);
            ral = *(const uint4*)(apbl + (it+1)*16);
            rwh = *(const uint4*)(wpbh + (size_t)(it+1)*16*D_);
            rwl = *(const uint4*)(wpbl + (size_t)(it+1)*16*D_);
        }
        {
            wmma::fragment<wmma::matrix_a,16,16,16,__nv_bfloat16,wmma::row_major> ah[4], al[4];
            wmma::fragment<wmma::matrix_b,16,16,16,__nv_bfloat16,wmma::row_major> bh[2], bl[2];
            #pragma unroll
            for (int mi = 0; mi < 4; mi++){
                wmma::load_matrix_sync(ah[mi], &sAh[buf][wm + mi*16][0], 24);
                wmma::load_matrix_sync(al[mi], &sAl[buf][wm + mi*16][0], 24);
            }
            #pragma unroll
            for (int nj = 0; nj < 2; nj++){
                wmma::load_matrix_sync(bh[nj], &sWh[buf][0][wn + nj*16], 136);
                wmma::load_matrix_sync(bl[nj], &sWl[buf][0][wn + nj*16], 136);
            }
            #pragma unroll
            for (int mi = 0; mi < 4; mi++)
                #pragma unroll
                for (int nj = 0; nj < 2; nj++){
                    wmma::mma_sync(cf[mi][nj], ah[mi], bh[nj], cf[mi][nj]);
                    wmma::mma_sync(cf[mi][nj], ah[mi], bl[nj], cf[mi][nj]);
                    wmma::mma_sync(cf[mi][nj], al[mi], bh[nj], cf[mi][nj]);
                }
        }
        if (it + 1 < NIT_){
            int nxt = buf ^ 1;
            *(uint4*)&sAh[nxt][ar][ac] = rah;
            *(uint4*)&sAl[nxt][ar][ac] = ral;
            *(uint4*)&sWh[nxt][wr][wc] = rwh;
            *(uint4*)&sWl[nxt][wr][wc] = rwl;
        }
        __syncthreads();
    }

    #pragma unroll
    for (int mi = 0; mi < 4; mi++){
        #pragma unroll
        for (int nj = 0; nj < 2; nj++){
            int r = rowBase + wm + mi*16;
            int cc = colBase + wn + nj*16;
            if (JOB == 3){
                wmma::store_matrix_sync(Cout + (size_t)r * D_ + cc, cf[mi][nj], D_, wmma::mem_row_major);
            } else {
                float* Dst = (JOB==0) ? &g_q[0] : (JOB==1) ? &g_k[0] : &g_v[0];
                #pragma unroll
                for (int e = 0; e < cf[mi][nj].num_elements; e++){
                    float x = cf[mi][nj].x[e];
                    cf[mi][nj].x[e] = x * sigm(x);
                }
                int b = r >> 12, l0 = r & (L_-1);
                int h = cc >> 6, d0 = cc & 63;
                float* p = Dst + (((size_t)(b*H_ + h)*L_ + l0) << 6) + d0;
                wmma::store_matrix_sync(p, cf[mi][nj], 64, wmma::mem_row_major);
            }
        }
    }
}

// ---------------- gate projections (proven) ----------------
__global__ __launch_bounds__(256) void gates_kernel(const float* __restrict__ x,
                                                    const float* __restrict__ fdb,
                                                    const float* __restrict__ sdb){
    __shared__ float xs[GTOK_][D_];
    int t0 = blockIdx.x * GTOK_;
    for(int i = threadIdx.x; i < GTOK_*D_/4; i += 256)
        ((float4*)&xs[0][0])[i] = ((const float4*)(x + (size_t)t0 * D_))[i];
    __syncthreads();
    int warp = threadIdx.x >> 5, lane = threadIdx.x & 31;
    for(int o = warp; o < 80; o += 8){
        int g = o >> 4, h = o & 15;
        const float* Wt = &g_WT[o*D_];
        float wreg[32];
        #pragma unroll
        for(int j=0;j<32;j++) wreg[j] = Wt[j*32 + lane];
        float accv[GTOK_];
        #pragma unroll
        for(int tt=0;tt<GTOK_;tt++) accv[tt]=0.f;
        #pragma unroll
        for(int j=0;j<32;j++){
            float w = wreg[j];
            #pragma unroll
            for(int tt=0;tt<GTOK_;tt++) accv[tt] += xs[tt][j*32+lane] * w;
        }
        #pragma unroll
        for(int tt=0;tt<GTOK_;tt++){
            float s = accv[tt];
            #pragma unroll
            for(int off=16;off;off>>=1) s += __shfl_xor_sync(0xffffffffu, s, off);
            if(lane == 0){
                int t = t0 + tt, b = t >> 12, l = t & (L_-1);
                float bias = (g==1)?fdb[h] : (g==2)?sdb[h] : 0.f;
                float val = sigm(s + bias);
                int idx = (b*H_ + h)*L_ + l;
                if(g==0) g_beta[idx]=val; else if(g==1) g_fd[idx]=val;
                else if(g==2) g_sd[idx]=val; else if(g==3) g_fg[idx]=val;
                else g_sg[idx]=val;
            }
        }
    }
}

// ---------------- per-token prep ----------------
__global__ __launch_bounds__(128) void prep_kernel(){
    __shared__ float fw[CH_], sw[CH_];
    int bh = blockIdx.x >> 5, c = blockIdx.x & 31;
    int t = threadIdx.x;
    int gidx = bh*L_ + c*CH_ + t;
    size_t base = (size_t)gidx * HD_;
    float beta = g_beta[gidx];

    float kv=0.f, kk=0.f, vv=0.f;
    #pragma unroll 4
    for(int d4=0; d4<HD_/4; d4++){
        float4 k4 = *(const float4*)(g_k + base + d4*4);
        float4 v4 = *(const float4*)(g_v + base + d4*4);
        kv += k4.x*v4.x + k4.y*v4.y + k4.z*v4.z + k4.w*v4.w;
        kk += k4.x*k4.x + k4.y*k4.y + k4.z*k4.z + k4.w*k4.w;
        vv += v4.x*v4.x + v4.y*v4.y + v4.z*v4.z + v4.w*v4.w;
    }
    float b2 = beta*beta;
    float nk = sqrtf(kk*b2) + 1e-8f;
    float nv = sqrtf(vv*b2) + 1e-8f;
    float psi_raw = fabsf(kv*b2) / (nk*nv);
    float psi  = sigm(3.0f * psi_raw);
    g_psi[gidx] = psi;
    fw[t] = g_fd[gidx] * (1.0f - 0.10f*psi);
    sw[t] = g_sd[gidx] * (1.0f - 0.05f*psi);

    // scale k,v by beta in place
    #pragma unroll 4
    for(int d4=0; d4<HD_/4; d4++){
        float4 k4 = *(const float4*)(g_k + base + d4*4);
        float4 v4 = *(const float4*)(g_v + base + d4*4);
        k4.x*=beta; k4.y*=beta; k4.z*=beta; k4.w*=beta;
        v4.x*=beta; v4.y*=beta; v4.z*=beta; v4.w*=beta;
        *(float4*)(g_k + base + d4*4) = k4;
        *(float4*)(g_v + base + d4*4) = v4;
    }
    __syncthreads();
    for(int off=64; off; off>>=1){
        if(t < off){ fw[t] += fw[t+off]; sw[t] += sw[t+off]; }
        __syncthreads();
    }
    if(t == 0){
        g_dff[blockIdx.x] = powf(fw[0] * (1.0f/CH_), (float)CH_);
        g_dfs[blockIdx.x] = powf(sw[0] * (1.0f/CH_), (float)CH_);
    }
}

// ---------------- fused dual-pass per-chunk outer products (1024 CTAs) ----------------
// st_f = sum_l v_l (x) k_l ;  st_s = sum_l surp_l^2 * v_l (x) k_l
__global__ __launch_bounds__(256) void chunk_outer_kernel(){
    __shared__ float ksm[64][HD_];
    __shared__ float vsm[64][HD_];
    __shared__ float s2[CH_];
    int bh = blockIdx.x >> 5, c = blockIdx.x & 31;
    int tid = threadIdx.x, ty = tid >> 4, tx = tid & 15;
    if (tid < CH_){
        float psi = g_psi[bh*L_ + c*CH_ + tid];
        float surp = sigm(10.0f * (psi - 0.5f));
        s2[tid] = surp * surp;
    }
    float stf[4][4], sts[4][4];
    #pragma unroll
    for(int i=0;i<4;i++)
        #pragma unroll
        for(int j=0;j<4;j++){ stf[i][j]=0.f; sts[i][j]=0.f; }

    #pragma unroll 1
    for(int half = 0; half < 2; half++){
        size_t base = ((size_t)bh*L_ + c*CH_ + half*64) * HD_;
        __syncthreads();
        for(int i = tid; i < 64*HD_/4; i += 256){
            ((float4*)&ksm[0][0])[i] = ((const float4*)(&g_k[0] + base))[i];
            ((float4*)&vsm[0][0])[i] = ((const float4*)(&g_v[0] + base))[i];
        }
        __syncthreads();
        #pragma unroll 2
        for(int l = 0; l < 64; l++){
            float sc = s2[half*64 + l];
            float4 v4 = *(float4*)&vsm[l][ty*4];
            float4 k4 = *(float4*)&ksm[l][tx*4];
            float4 vs = make_float4(v4.x*sc, v4.y*sc, v4.z*sc, v4.w*sc);
            stf[0][0]+=v4.x*k4.x; stf[0][1]+=v4.x*k4.y; stf[0][2]+=v4.x*k4.z; stf[0][3]+=v4.x*k4.w;
            stf[1][0]+=v4.y*k4.x; stf[1][1]+=v4.y*k4.y; stf[1][2]+=v4.y*k4.z; stf[1][3]+=v4.y*k4.w;
            stf[2][0]+=v4.z*k4.x; stf[2][1]+=v4.z*k4.y; stf[2][2]+=v4.z*k4.z; stf[2][3]+=v4.z*k4.w;
            stf[3][0]+=v4.w*k4.x; stf[3][1]+=v4.w*k4.y; stf[3][2]+=v4.w*k4.z; stf[3][3]+=v4.w*k4.w;
            sts[0][0]+=vs.x*k4.x; sts[0][1]+=vs.x*k4.y; sts[0][2]+=vs.x*k4.z; sts[0][3]+=vs.x*k4.w;
            sts[1][0]+=vs.y*k4.x; sts[1][1]+=vs.y*k4.y; sts[1][2]+=vs.y*k4.z; sts[1][3]+=vs.y*k4.w;
            sts[2][0]+=vs.z*k4.x; sts[2][1]+=vs.z*k4.y; sts[2][2]+=vs.z*k4.z; sts[2][3]+=vs.z*k4.w;
            sts[3][0]+=vs.w*k4.x; sts[3][1]+=vs.w*k4.y; sts[3][2]+=vs.w*k4.z; sts[3][3]+=vs.w*k4.w;
        }
    }
    float* spf = &g_state[0] + (size_t)(bh*NCH_ + c) * (HD_*HD_);
    float* sps = &g_state[0] + (size_t)((BH_ + bh)*NCH_ + c) * (HD_*HD_);
    #pragma unroll
    for(int i=0;i<4;i++){
        *(float4*)(spf + (ty*4+i)*HD_ + tx*4) = make_float4(stf[i][0], stf[i][1], stf[i][2], stf[i][3]);
        *(float4*)(sps + (ty*4+i)*HD_ + tx*4) = make_float4(sts[i][0], sts[i][1], sts[i][2], sts[i][3]);
    }
}

// ---------------- serial recurrence in-place: state_c = df_c*state_{c-1} + S_c ----------------
__global__ __launch_bounds__(256) void scan2_kernel(){
    int pass = blockIdx.x >> 5, bh = blockIdx.x & 31;
    const float* dfp = pass ? &g_dfs[0] : &g_dff[0];
    float* base = &g_state[0] + (size_t)blockIdx.x * NCH_ * (HD_*HD_);
    int off = threadIdx.x * 16;
    float4 st0 = make_float4(0,0,0,0), st1 = st0, st2 = st0, st3 = st0;
    for(int c = 0; c < NCH_; c++){
        float df = dfp[bh*NCH_ + c];
        float* p = base + (size_t)c * (HD_*HD_) + off;
        float4 s0 = *(float4*)(p+0), s1 = *(float4*)(p+4);
        float4 s2 = *(float4*)(p+8), s3 = *(float4*)(p+12);
        st0.x = st0.x*df + s0.x; st0.y = st0.y*df + s0.y; st0.z = st0.z*df + s0.z; st0.w = st0.w*df + s0.w;
        st1.x = st1.x*df + s1.x; st1.y = st1.y*df + s1.y; st1.z = st1.z*df + s1.z; st1.w = st1.w*df + s1.w;
        st2.x = st2.x*df + s2.x; st2.y = st2.y*df + s2.y; st2.z = st2.z*df + s2.z; st2.w = st2.w*df + s2.w;
        st3.x = st3.x*df + s3.x; st3.y = st3.y*df + s3.y; st3.z = st3.z*df + s3.z; st3.w = st3.w*df + s3.w;
        *(float4*)(p+0) = st0; *(float4*)(p+4) = st1;
        *(float4*)(p+8) = st2; *(float4*)(p+12) = st3;
    }
}

// ---------------- per-chunk output + gated combine (proven) ----------------
__global__ __launch_bounds__(256) void o_kernel(){
    __shared__ float qsm[CH_][HD_];
    __shared__ float stm[HD_][HD_];
    int bh = blockIdx.x >> 5, c = blockIdx.x & 31;
    int b = bh >> 4, h = bh & 15;
    int tid = threadIdx.x, ly = tid >> 4, dx = tid & 15;
    size_t qbase = ((size_t)bh*L_ + c*CH_) * HD_;
    for(int i = tid; i < CH_*HD_/4; i += 256)
        ((float4*)&qsm[0][0])[i] = ((const float4*)(&g_q[0] + qbase))[i];

    float accf[8][4], accs[8][4];
    {
        size_t sb = ((size_t)bh*NCH_ + c) * (HD_*HD_);
        for(int i = tid; i < HD_*HD_/4; i += 256)
            ((float4*)&stm[0][0])[i] = ((const float4*)(&g_state[0] + sb))[i];
        __syncthreads();
        #pragma unroll
        for(int i=0;i<8;i++){ accf[i][0]=0;accf[i][1]=0;accf[i][2]=0;accf[i][3]=0; }
        for(int d = 0; d < HD_; d++){
            float4 s4 = *(float4*)&stm[d][dx*4];
            #pragma unroll
            for(int i=0;i<8;i++){
                float qv = qsm[ly*8+i][d];
                accf[i][0]+=qv*s4.x; accf[i][1]+=qv*s4.y;
                accf[i][2]+=qv*s4.z; accf[i][3]+=qv*s4.w;
            }
        }
        __syncthreads();
    }
    {
        size_t sb = ((size_t)(BH_ + bh)*NCH_ + c) * (HD_*HD_);
        for(int i = tid; i < HD_*HD_/4; i += 256)
            ((float4*)&stm[0][0])[i] = ((const float4*)(&g_state[0] + sb))[i];
        __syncthreads();
        #pragma unroll
        for(int i=0;i<8;i++){ accs[i][0]=0;accs[i][1]=0;accs[i][2]=0;accs[i][3]=0; }
        for(int d = 0; d < HD_; d++){
            float4 s4 = *(float4*)&stm[d][dx*4];
            #pragma unroll
            for(int i=0;i<8;i++){
                float qv = qsm[ly*8+i][d];
                accs[i][0]+=qv*s4.x; accs[i][1]+=qv*s4.y;
                accs[i][2]+=qv*s4.z; accs[i][3]+=qv*s4.w;
            }
        }
    }
    #pragma unroll
    for(int i=0;i<8;i++){
        int l = ly*8 + i;
        int gidx = bh*L_ + c*CH_ + l;
        float psi = g_psi[gidx];
        float a   = 0.5f + 0.3f*psi;
        float fa  = a * g_fg[gidx];
        float sa  = (1.0f - a) * g_sg[gidx];
        float4 o;
        o.x = fa*accf[i][0] + sa*accs[i][0];
        o.y = fa*accf[i][1] + sa*accs[i][1];
        o.z = fa*accf[i][2] + sa*accs[i][2];
        o.w = fa*accf[i][3] + sa*accs[i][3];
        *(float4*)(&g_oc[0] + ((size_t)(b*L_ + c*CH_ + l))*D_ + h*HD_ + dx*4) = o;
    }
}

// ---------------- launch (ONLY harness pointers passed as args) ----------------
extern "C" void kernel_launch(void* const* d_in, const int* in_sizes, int n_in,
                              void* d_out, int out_size){
    const float* x   = (const float*)d_in[0];
    const float* Wq  = (const float*)d_in[1];
    const float* Wk  = (const float*)d_in[2];
    const float* Wv  = (const float*)d_in[3];
    const float* Wb  = (const float*)d_in[4];
    const float* Wfd = (const float*)d_in[5];
    const float* fdb = (const float*)d_in[6];
    const float* Wsd = (const float*)d_in[7];
    const float* sdb = (const float*)d_in[8];
    const float* Wfg = (const float*)d_in[9];
    const float* Wsg = (const float*)d_in[10];
    const float* Wo  = (const float*)d_in[11];
    float* out = (float*)d_out;

    dim3 tg(D_/128, TOK_/128);           // (8, 64)

    wt_kernel<<<80, 256>>>(Wb, Wfd, Wsd, Wfg, Wsg);
    split_pair_kernel<0><<<TOK_*D_/8/256, 256>>>(x);
    split_w_kernel<<<dim3(D_*D_/8/256, 4), 256>>>(Wq, Wk, Wv, Wo);
    wgemm_kernel<0><<<tg, 256>>>(nullptr);   // q = silu(x@Wq)
    wgemm_kernel<1><<<tg, 256>>>(nullptr);   // k
    wgemm_kernel<2><<<tg, 256>>>(nullptr);   // v
    gates_kernel<<<TOK_/GTOK_, 256>>>(x, fdb, sdb);
    prep_kernel<<<BH_*NCH_, 128>>>();
    chunk_outer_kernel<<<BH_*NCH_, 256>>>();
    scan2_kernel<<<2*BH_, 256>>>();
    o_kernel<<<BH_*NCH_, 256>>>();
    split_pair_kernel<1><<<TOK_*D_/8/256, 256>>>(nullptr);
    wgemm_kernel<3><<<tg, 256>>>(out);       // out = oc @ Wo
}